// round 15
// baseline (speedup 1.0000x reference)
#include <cuda_runtime.h>

#define HH 1024
#define WW 1024
#define NC 128
#define NITER 8
#define NBLKP 128      // persistent blocks, all resident (128 <= 148 SMs)
#define TPB 1024
#define TPBLK 8        // 32x32 tiles per block (8 horizontally adjacent)
#define REPS 8         // shared accumulator replicas
#define NGRP 8         // barrier fan-in groups (16 blocks each)

// Cross-block state. g_part2: double-buffered per-block partials, fully
// rewritten each iteration (no zeroing needed). Barrier counters are reset
// by their last arriver each use -> zeroed at kernel exit (graph-replay safe).
// g_gen is monotonic across launches (entry snapshot).
__device__ float2   g_part2[2][NBLKP][NC];
__device__ unsigned g_agrp[NGRP * 32];   // one counter per 128B line
__device__ unsigned g_aroot;
__device__ unsigned g_gen;

__device__ __forceinline__ unsigned coord_hash(float2 c)
{
    unsigned hx = __float_as_uint(c.x), hy = __float_as_uint(c.y);
    unsigned h = hx * 2654435761u ^ hy * 40503u;
    return (h ^ (h >> 16)) & 255u;
}

__global__ __launch_bounds__(TPB, 1)
void kmeans_persist(const float* __restrict__ clusters,
                    const float* __restrict__ heat,
                    float2* __restrict__ out)
{
    __shared__ float2   s_scl[TPBLK][NC];   // survivors; tail reuses as scratch
    __shared__ int      s_sidx[TPBLK][NC];
    __shared__ float2   s_acc[REPS][NC];
    __shared__ float2   s_red[8][NC];
    __shared__ float2   s_tmp[NC];
    __shared__ int      s_hslot[256];
    __shared__ int      s_ns[TPBLK];
    __shared__ unsigned s_base;

    const int tid  = threadIdx.x;
    const int bid  = blockIdx.x;
    const int wid  = tid >> 5;
    const int lane = tid & 31;
    const unsigned full = 0xffffffffu;

    // gen snapshot BEFORE first arrival (gen cannot bump until all arrive)
    if (tid == 0) s_base = *(volatile unsigned*)&g_gen;

    // Tile geometry: linear tile tl = bid*8 + t; row tr = tl>>5 is the same
    // for all 8 tiles of a block; warp = pixel row, lane = pixel col.
    const int tl0  = bid * TPBLK;
    const int tr   = tl0 >> 5;
    const int grow = tr * 32 + wid;
    const float fi = (float)grow;

    // ---- heatmap -> registers, once for the whole run ----
    float h[TPBLK];
    #pragma unroll
    for (int t = 0; t < TPBLK; ++t)
        h[t] = heat[grow * WW + ((tl0 + t) & 31) * 32 + lane];

    // ---- one-time smem init (later re-inited inside the barrier window) ----
    if (tid < 256) s_hslot[tid] = 1 << 30;
    ((float2*)s_acc)[tid] = make_float2(0.f, 0.f);
    __syncthreads();                     // S0: publishes s_base + inits
    const unsigned base = s_base;

    for (int it = 0; it < NITER; ++it) {
        // ===== A: partial group sums (it>0): 8 groups x 16 blocks ===========
        const int cc = tid & 127;        // cluster id
        const int rg = tid >> 7;         // group 0..7
        if (it > 0) {
            const int p = (it - 1) & 1;
            float sx = 0.f, sy = 0.f;
            #pragma unroll
            for (int r = 0; r < 16; ++r) {      // blocks rg, rg+8, ..., rg+120
                float2 v = g_part2[p][rg + r * 8][cc];
                sx += v.x; sy += v.y;
            }
            s_red[rg][cc] = make_float2(sx, sy);
            __syncthreads();                                        // S1
        }

        // ===== B: final cluster coords + hash arbitration ===================
        if (tid < NC) {
            float2 cs;
            if (it == 0) {
                cs = ((const float2*)clusters)[tid];
            } else {
                float x = 0.f, y = 0.f;
                #pragma unroll
                for (int r = 0; r < 8; ++r) { x += s_red[r][tid].x; y += s_red[r][tid].y; }
                cs = make_float2(x, y);
            }
            s_tmp[tid] = cs;
            atomicMin(&s_hslot[coord_hash(cs)], tid);
        }
        __syncthreads();                                            // S2

        // ===== C: warp-private prune+dedup (warp w handles tile w, w<8) =====
        // Dedup folded in: identical coords at a LOWER index can never win
        // the strict-< argmin -> drop (exact). A hash collision only MISSES
        // a dedup, harmless: survivors remain in ascending original index.
        if (wid < TPBLK) {
            const float cy = (float)(tr * 32) + 15.5f;
            const float cx = (float)(((tl0 + wid) & 31) * 32) + 15.5f;
            float  cd2[4];
            float2 ccl[4];
            float  mn = 3.4e38f;
            #pragma unroll
            for (int k = 0; k < 4; ++k) {
                int c = k * 32 + lane;
                ccl[k] = s_tmp[c];
                float dr = cy - ccl[k].x, dc = cx - ccl[k].y;
                cd2[k] = __fadd_rn(__fmul_rn(dr, dr), __fmul_rn(dc, dc));
                mn = fminf(mn, cd2[k]);
            }
            #pragma unroll
            for (int o = 16; o; o >>= 1) mn = fminf(mn, __shfl_xor_sync(full, mn, o));
            // keep c iff dist(center,c) <= min + 2r (+margin); r=15.5*sqrt2
            float thr  = sqrtf(mn) + 44.9f;
            float thr2 = thr * thr;
            int cnt = 0;
            #pragma unroll
            for (int k = 0; k < 4; ++k) {
                int c = k * 32 + lane;
                bool uniq = true;
                int w = s_hslot[coord_hash(ccl[k])];
                if (w < c) {
                    float2 o2 = s_tmp[w];
                    uniq = !((o2.x == ccl[k].x) & (o2.y == ccl[k].y));
                }
                bool p = uniq && (cd2[k] <= thr2);
                unsigned pb = __ballot_sync(full, p);
                if (p) {
                    int pos = cnt + __popc(pb & ((1u << lane) - 1u));
                    s_scl[wid][pos]  = ccl[k];
                    s_sidx[wid][pos] = c;        // ascending original index
                }
                cnt += __popc(pb);
            }
            if (lane == 0) s_ns[wid] = cnt;
        }
        __syncthreads();                                            // S3

        // ===== D: pixel pass (register run-accumulation) ====================
        int   curidx = -1;
        float ax = 0.f, ay = 0.f;
        const int repl = lane & (REPS - 1);   // per-thread flushes: lane-spread
        const int repw = wid  & (REPS - 1);   // warp-collective flush: warp-spread
        #pragma unroll
        for (int t = 0; t < TPBLK; ++t) {
            const int   ns = s_ns[t];
            const float fj = (float)(((tl0 + t) & 31) * 32 + lane);
            float best; int bs;
            if (ns == 1) {                       // dominant post-collapse case
                float2 c2 = s_scl[t][0];
                float dr = fi - c2.x, dc = fj - c2.y;
                best = fmaxf(__fadd_rn(__fmul_rn(dr, dr), __fmul_rn(dc, dc)), 1.0f);
                bs = 0;
            } else {
                best = 3.4e38f; bs = 0;
                for (int s = 0; s < ns; ++s) {
                    float2 c2 = s_scl[t][s];
                    float dr = fi - c2.x, dc = fj - c2.y;
                    // match reference: dr*dr + dc*dc (no fma), clamp >= 1
                    float d2 = fmaxf(__fadd_rn(__fmul_rn(dr, dr), __fmul_rn(dc, dc)), 1.0f);
                    if (d2 < best) { best = d2; bs = s; }
                }
            }
            float w = h[t] * __frsqrt_rn(best);
            int ci = s_sidx[t][bs];
            if (ci != curidx) {
                if (curidx >= 0) {
                    atomicAdd(&s_acc[repl][curidx].x, ax);
                    atomicAdd(&s_acc[repl][curidx].y, ay);
                }
                curidx = ci; ax = 0.f; ay = 0.f;
            }
            ax = __fmaf_rn(fi, w, ax);
            ay = __fmaf_rn(fj, w, ay);
        }
        {   // final flush: warp-uniform fast path
            int  sref = __shfl_sync(full, curidx, 0);
            bool uni  = __all_sync(full, curidx == sref);
            if (uni) {
                #pragma unroll
                for (int o = 16; o; o >>= 1) {
                    ax += __shfl_xor_sync(full, ax, o);
                    ay += __shfl_xor_sync(full, ay, o);
                }
                if (lane == 0) {
                    atomicAdd(&s_acc[repw][sref].x, ax);
                    atomicAdd(&s_acc[repw][sref].y, ay);
                }
            } else {
                atomicAdd(&s_acc[repl][curidx].x, ax);
                atomicAdd(&s_acc[repl][curidx].y, ay);
            }
        }
        __syncthreads();                                            // S4

        // ===== E: write partials (plain stores, deterministic) ==============
        if (tid < NC) {
            float x = 0.f, y = 0.f;
            #pragma unroll
            for (int r = 0; r < REPS; ++r) { x += s_acc[r][tid].x; y += s_acc[r][tid].y; }
            g_part2[it & 1][bid][tid] = make_float2(x, y);
        }
        __syncthreads();                                            // S5

        // ===== F: fan-in barrier; smem re-init overlaps the wait ============
        if (tid == 0) {
            __threadfence();                         // release our partials
            const int g = bid >> 4;
            unsigned o = atomicAdd(&g_agrp[g * 32], 1u);
            if (o == 15u) {                          // last of the group
                *(volatile unsigned*)&g_agrp[g * 32] = 0u;  // reset before root
                __threadfence();
                unsigned r = atomicAdd(&g_aroot, 1u);
                if (r == (unsigned)(NGRP - 1)) {     // last group overall
                    *(volatile unsigned*)&g_aroot = 0u;
                    __threadfence();
                    atomicAdd(&g_gen, 1u);
                }
            }
        }
        // next-iteration smem init, overlapped with other blocks' arrival
        if (tid < 256) s_hslot[tid] = 1 << 30;
        ((float2*)s_acc)[tid] = make_float2(0.f, 0.f);
        if (tid == 0) {
            if (bid == 0 || it < NITER - 1) {
                while ((int)(*(volatile unsigned*)&g_gen - base) < it + 1)
                    __nanosleep(32);
            }
            __threadfence();                         // acquire
        }
        __syncthreads();                                            // S6
    }

    // ===== tail: block 0 reduces the last buffer into d_out =================
    if (bid == 0) {
        const int p  = (NITER - 1) & 1;
        const int cc = tid & 127, rg = tid >> 7;
        float sx = 0.f, sy = 0.f;
        #pragma unroll
        for (int r = 0; r < 16; ++r) {
            float2 v = g_part2[p][rg + r * 8][cc];
            sx += v.x; sy += v.y;
        }
        s_scl[rg][cc] = make_float2(sx, sy);         // reuse as scratch
        __syncthreads();
        if (tid < NC) {
            float x = 0.f, y = 0.f;
            #pragma unroll
            for (int r = 0; r < 8; ++r) { x += s_scl[r][tid].x; y += s_scl[r][tid].y; }
            out[tid] = make_float2(x, y);
        }
    }
}

extern "C" void kernel_launch(void* const* d_in, const int* in_sizes, int n_in,
                              void* d_out, int out_size)
{
    // Identify inputs by size: clusters = 256 elems, heatmap = 1M.
    const float* clusters = (const float*)d_in[0];
    const float* heat     = (const float*)d_in[1];
    if (in_sizes[0] != NC * 2) {
        clusters = (const float*)d_in[1];
        heat     = (const float*)d_in[0];
    }
    kmeans_persist<<<NBLKP, TPB>>>(clusters, heat, (float2*)d_out);
}

// round 16
// speedup vs baseline: 1.4029x; 1.4029x over previous
#include <cuda_runtime.h>

#define HH 1024
#define WW 1024
#define NC 128
#define NITER 8
#define NBLKP 128      // persistent blocks, all resident (128 <= 148 SMs)
#define TPB 1024
#define TPBLK 8        // 32x32 tiles per block (8 horizontally adjacent)
#define REPS 8         // shared accumulator replicas

// Cross-block state. g_part2: double-buffered per-block partials, fully
// rewritten each iteration (no zeroing needed). g_gen monotonic across
// launches (entry snapshot); g_arrive left at 0 by the last arriver.
// g_ccoord/g_csum/g_cvalid: block-private uniform-pass cache, invalidated
// at kernel entry (replay-deterministic).
__device__ float2   g_part2[2][NBLKP][NC];
__device__ unsigned g_gen;
__device__ unsigned g_arrive;
__device__ float2   g_ccoord[NBLKP];
__device__ float2   g_csum[NBLKP];
__device__ int      g_cvalid[NBLKP];

__device__ __forceinline__ unsigned coord_hash(float2 c)
{
    unsigned hx = __float_as_uint(c.x), hy = __float_as_uint(c.y);
    unsigned h = hx * 2654435761u ^ hy * 40503u;
    return (h ^ (h >> 16)) & 255u;
}

__global__ __launch_bounds__(TPB, 1)
void kmeans_persist(const float* __restrict__ clusters,
                    const float* __restrict__ heat,
                    float2* __restrict__ out)
{
    __shared__ float2   s_scl[TPBLK][NC];
    __shared__ int      s_sidx[TPBLK][NC];
    __shared__ float2   s_acc[REPS][NC];
    __shared__ float2   s_red[8][NC];
    __shared__ float2   s_tmp[NC];
    __shared__ float2   s_cand[NC];
    __shared__ int      s_ci[NC];
    __shared__ int      s_hslot[256];
    __shared__ float    s_wm[TPBLK][4];
    __shared__ int      s_wc[TPBLK][4];
    __shared__ int      s_ns[TPBLK];
    __shared__ int      s_ncand;
    __shared__ float2   s_usum;
    __shared__ int      s_uhit;
    __shared__ unsigned s_base;

    const int tid  = threadIdx.x;
    const int bid  = blockIdx.x;
    const int wid  = tid >> 5;
    const int lane = tid & 31;
    const unsigned full = 0xffffffffu;

    // gen snapshot BEFORE first arrival (gen cannot bump until all arrive);
    // invalidate this block's cache for deterministic graph replay.
    if (tid == 0) { s_base = *(volatile unsigned*)&g_gen; g_cvalid[bid] = 0; }

    // Tile geometry: linear tile tl = bid*8 + t; row tr = tl>>5 is the same
    // for all 8 tiles of a block; warp = pixel row, lane = pixel col.
    const int tl0  = bid * TPBLK;
    const int tr   = tl0 >> 5;
    const int grow = tr * 32 + wid;
    const float fi = (float)grow;

    // ---- heatmap -> registers, once for the whole run ----
    float h[TPBLK];
    #pragma unroll
    for (int t = 0; t < TPBLK; ++t)
        h[t] = heat[grow * WW + ((tl0 + t) & 31) * 32 + lane];

    __syncthreads();                   // publishes s_base + cache invalidate
    const unsigned base = s_base;

    for (int it = 0; it < NITER; ++it) {
        // ================= candidate rebuild (every block, in parallel) =====
        const int cc = tid & 127;      // cluster id
        const int rg = tid >> 7;       // row group 0..7
        if (it == 0) {
            if (tid < NC) s_tmp[tid] = ((const float2*)clusters)[tid];
        } else {
            const int p = (it - 1) & 1;
            float sx = 0.f, sy = 0.f;
            #pragma unroll
            for (int r = 0; r < 16; ++r) {       // rows rg, rg+8, ..., rg+120
                float2 v = g_part2[p][rg + r * 8][cc];
                sx += v.x; sy += v.y;
            }
            s_red[rg][cc] = make_float2(sx, sy);
        }
        if (tid < 256) s_hslot[tid] = 1 << 30;
        __syncthreads();

        if (it > 0 && tid < NC) {
            float x = 0.f, y = 0.f;
            #pragma unroll
            for (int r = 0; r < 8; ++r) { x += s_red[r][tid].x; y += s_red[r][tid].y; }
            s_tmp[tid] = make_float2(x, y);
        }
        __syncthreads();

        float2   cs  = make_float2(0.f, 0.f);
        unsigned hsh = 0;
        if (tid < NC) { cs = s_tmp[tid]; hsh = coord_hash(cs); atomicMin(&s_hslot[hsh], tid); }
        __syncthreads();

        // Hash dedup: identical coords at a LOWER index can never win the
        // strict-< argmin -> drop (exact). A collision only MISSES a dedup,
        // which is harmless: survivors remain index-sorted.
        bool uniq = false;
        if (tid < NC) {
            uniq = true;
            int w = s_hslot[hsh];
            if (w < tid) { float2 o = s_tmp[w]; uniq = !((o.x == cs.x) & (o.y == cs.y)); }
        }
        unsigned bal = __ballot_sync(full, uniq);
        if (lane == 0 && tid < NC) s_wc[0][wid] = __popc(bal);
        __syncthreads();
        if (tid < NC) {
            int b = (wid > 0 ? s_wc[0][0] : 0) + (wid > 1 ? s_wc[0][1] : 0) + (wid > 2 ? s_wc[0][2] : 0);
            if (uniq) {
                int pos = b + __popc(bal & ((1u << lane) - 1u));
                s_cand[pos] = cs; s_ci[pos] = tid;    // ascending original index
            }
            if (tid == 0) s_ncand = s_wc[0][0] + s_wc[0][1] + s_wc[0][2] + s_wc[0][3];
        }
        __syncthreads();

        // ================= per-tile pruning preamble ========================
        const int ncand = s_ncand;
        const int ts = tid >> 7;       // tile slot 0..7
        float  cd2 = 3.4e38f;
        float2 cl  = make_float2(0.f, 0.f);
        int    cidx = 0;
        if (cc < ncand) {
            cl = s_cand[cc]; cidx = s_ci[cc];
            float cy = (float)(tr * 32) + 15.5f;
            float cx = (float)(((tl0 + ts) & 31) * 32) + 15.5f;
            float dr = cy - cl.x, dc = cx - cl.y;
            cd2 = __fadd_rn(__fmul_rn(dr, dr), __fmul_rn(dc, dc));
        }
        float m = cd2;
        #pragma unroll
        for (int o = 16; o; o >>= 1) m = fminf(m, __shfl_xor_sync(full, m, o));
        if (lane == 0) s_wm[ts][wid & 3] = m;
        ((float2*)s_acc)[tid] = make_float2(0.f, 0.f);   // zero smem replicas
        __syncthreads();

        float mind2 = fminf(fminf(s_wm[ts][0], s_wm[ts][1]),
                            fminf(s_wm[ts][2], s_wm[ts][3]));
        // keep c iff dist(center,c) <= min + 2r (+margin); r=15.5*sqrt2, 2r=43.84
        float thr = sqrtf(mind2) + 44.9f;
        bool pred = (cc < ncand) && (cd2 <= thr * thr);
        unsigned pb = __ballot_sync(full, pred);
        if (lane == 0) s_wc[ts][wid & 3] = __popc(pb);
        __syncthreads();
        {
            int wig = wid & 3;
            int b = (wig > 0 ? s_wc[ts][0] : 0) + (wig > 1 ? s_wc[ts][1] : 0) + (wig > 2 ? s_wc[ts][2] : 0);
            if (pred) {
                int pos = b + __popc(pb & ((1u << lane) - 1u));
                s_scl[ts][pos]  = cl;
                s_sidx[ts][pos] = cidx;      // ascending original index
            }
            if (cc == 0) s_ns[ts] = s_wc[ts][0] + s_wc[ts][1] + s_wc[ts][2] + s_wc[ts][3];
        }
        __syncthreads();

        // ===== uniform-block detection (pure smem reads, block-uniform) =====
        bool ub = true;
        float2 uc = s_scl[0][0];
        #pragma unroll
        for (int t = 0; t < TPBLK; ++t) {
            ub &= (s_ns[t] == 1);
            float2 ct = s_scl[t][0];
            ub &= (__float_as_uint(ct.x) == __float_as_uint(uc.x)) &
                  (__float_as_uint(ct.y) == __float_as_uint(uc.y));
        }

        if (ub) {
            // single survivor, identical coords in all 8 tiles -> one winner
            // index block-wide; sums depend only on coords -> cacheable.
            const int k = s_sidx[0][0];
            if (tid == 0) {
                int hit = g_cvalid[bid] &&
                          (__float_as_uint(g_ccoord[bid].x) == __float_as_uint(uc.x)) &&
                          (__float_as_uint(g_ccoord[bid].y) == __float_as_uint(uc.y));
                s_uhit = hit;
                if (hit) s_usum = g_csum[bid];
            }
            __syncthreads();
            if (!s_uhit) {
                float ax = 0.f, ay = 0.f;
                const float dr  = fi - uc.x;
                const float dr2 = __fmul_rn(dr, dr);
                #pragma unroll
                for (int t = 0; t < TPBLK; ++t) {
                    const float fj = (float)(((tl0 + t) & 31) * 32 + lane);
                    float dc = fj - uc.y;
                    // match reference: dr*dr + dc*dc (no fma), clamp >= 1
                    float d2 = fmaxf(__fadd_rn(dr2, __fmul_rn(dc, dc)), 1.0f);
                    float w  = h[t] * __frsqrt_rn(d2);
                    ax = __fmaf_rn(fi, w, ax);
                    ay = __fmaf_rn(fj, w, ay);
                }
                #pragma unroll
                for (int o = 16; o; o >>= 1) {
                    ax += __shfl_xor_sync(full, ax, o);
                    ay += __shfl_xor_sync(full, ay, o);
                }
                if (lane == 0) s_red[0][wid] = make_float2(ax, ay);
                __syncthreads();
                if (wid == 0) {
                    float2 v = s_red[0][lane];
                    float sx = v.x, sy = v.y;
                    #pragma unroll
                    for (int o = 16; o; o >>= 1) {
                        sx += __shfl_xor_sync(full, sx, o);
                        sy += __shfl_xor_sync(full, sy, o);
                    }
                    if (lane == 0) {
                        s_usum = make_float2(sx, sy);
                        g_csum[bid]   = make_float2(sx, sy);
                        g_ccoord[bid] = uc;
                        g_cvalid[bid] = 1;
                    }
                }
                __syncthreads();
            }
            if (tid < NC) {
                float2 v = (tid == k) ? s_usum : make_float2(0.f, 0.f);
                g_part2[it & 1][bid][tid] = v;
            }
        } else {
            // ============== generic pixel pass (register run-accumulation) ==
            int   curidx = -1;
            float ax = 0.f, ay = 0.f;
            const int rep = wid & (REPS - 1);
            #pragma unroll
            for (int t = 0; t < TPBLK; ++t) {
                const int   ns = s_ns[t];
                const float fj = (float)(((tl0 + t) & 31) * 32 + lane);
                float best; int bs;
                if (ns == 1) {
                    float2 c2 = s_scl[t][0];
                    float dr = fi - c2.x, dc = fj - c2.y;
                    best = fmaxf(__fadd_rn(__fmul_rn(dr, dr), __fmul_rn(dc, dc)), 1.0f);
                    bs = 0;
                } else {
                    best = 3.4e38f; bs = 0;
                    for (int s = 0; s < ns; ++s) {
                        float2 c2 = s_scl[t][s];
                        float dr = fi - c2.x, dc = fj - c2.y;
                        // match reference: dr*dr + dc*dc (no fma), clamp >= 1
                        float d2 = fmaxf(__fadd_rn(__fmul_rn(dr, dr), __fmul_rn(dc, dc)), 1.0f);
                        if (d2 < best) { best = d2; bs = s; }
                    }
                }
                float w = h[t] * __frsqrt_rn(best);
                int ci = s_sidx[t][bs];
                if (ci != curidx) {
                    if (curidx >= 0) {
                        atomicAdd(&s_acc[rep][curidx].x, ax);
                        atomicAdd(&s_acc[rep][curidx].y, ay);
                    }
                    curidx = ci; ax = 0.f; ay = 0.f;
                }
                ax = __fmaf_rn(fi, w, ax);
                ay = __fmaf_rn(fj, w, ay);
            }
            {   // warp-uniform final flush
                int  sref = __shfl_sync(full, curidx, 0);
                bool uni  = __all_sync(full, curidx == sref);
                if (uni) {
                    #pragma unroll
                    for (int o = 16; o; o >>= 1) {
                        ax += __shfl_xor_sync(full, ax, o);
                        ay += __shfl_xor_sync(full, ay, o);
                    }
                    if (lane == 0) {
                        atomicAdd(&s_acc[rep][sref].x, ax);
                        atomicAdd(&s_acc[rep][sref].y, ay);
                    }
                } else {
                    atomicAdd(&s_acc[rep][curidx].x, ax);
                    atomicAdd(&s_acc[rep][curidx].y, ay);
                }
            }
            __syncthreads();

            // write this block's 128 partials (plain stores, no atomics)
            if (tid < NC) {
                float x = 0.f, y = 0.f;
                #pragma unroll
                for (int r = 0; r < REPS; ++r) { x += s_acc[r][tid].x; y += s_acc[r][tid].y; }
                g_part2[it & 1][bid][tid] = make_float2(x, y);
            }
        }

        // ================= bare grid barrier (empty critical section) =======
        __syncthreads();
        if (tid == 0) {
            __threadfence();                       // release our partials
            unsigned old = atomicAdd(&g_arrive, 1u);
            if (old == NBLKP - 1) {
                *(volatile unsigned*)&g_arrive = 0u;   // reset for next barrier
                __threadfence();
                atomicAdd(&g_gen, 1u);
            } else if (bid == 0 || it < NITER - 1) {
                // non-zero blocks skip the final poll and just exit
                while ((int)(*(volatile unsigned*)&g_gen - base) < it + 1)
                    __nanosleep(32);
            }
            __threadfence();                       // acquire
        }
        __syncthreads();
    }

    // ================= tail: block 0 reduces the last buffer ================
    if (bid == 0) {
        const int p = (NITER - 1) & 1;
        const int cc = tid & 127, rg = tid >> 7;
        float sx = 0.f, sy = 0.f;
        #pragma unroll
        for (int r = 0; r < 16; ++r) {
            float2 v = g_part2[p][rg + r * 8][cc];
            sx += v.x; sy += v.y;
        }
        s_red[rg][cc] = make_float2(sx, sy);
        __syncthreads();
        if (tid < NC) {
            float x = 0.f, y = 0.f;
            #pragma unroll
            for (int r = 0; r < 8; ++r) { x += s_red[r][tid].x; y += s_red[r][tid].y; }
            out[tid] = make_float2(x, y);
        }
    }
}

extern "C" void kernel_launch(void* const* d_in, const int* in_sizes, int n_in,
                              void* d_out, int out_size)
{
    // Identify inputs by size: clusters = 256 elems, heatmap = 1M.
    const float* clusters = (const float*)d_in[0];
    const float* heat     = (const float*)d_in[1];
    if (in_sizes[0] != NC * 2) {
        clusters = (const float*)d_in[1];
        heat     = (const float*)d_in[0];
    }
    kmeans_persist<<<NBLKP, TPB>>>(clusters, heat, (float2*)d_out);
}